// round 6
// baseline (speedup 1.0000x reference)
#include <cuda_runtime.h>
#include <cuda_fp16.h>
#include <cstdint>

// fp16 2-pass "exact-A" tensor-core version (mma.sync m16n8k16 f16, sm_80 PTX).
//   X[128x128] = [features2[topk] | features1]  (8 queries x 16 nbrs = 128 rows)
//   H = ELU(X@W1+b1); Y = ELU(H@W2+b2); out[q] = sum_k w[q,k] * Y[q*16+k]
// GEMM: D(fp32) = Xh*Wh + Xl*Wh = (Xh+Xl)*Wh = X*Wh  (A exact; err = W fp16 rounding)

namespace {
constexpr int kN1      = 50000;
constexpr int kNN      = 16;
constexpr int kQPB     = 8;
constexpr int kTiles   = kN1 / kQPB;   // 6250
constexpr int kThreads = 256;
constexpr int kGrid    = 148;

// SMEM byte offsets
constexpr int SM_ROWW  = 0;            // 128 f32
constexpr int SM_B1    = 512;          // 128 f32
constexpr int SM_B2    = 1024;         // 128 f32
constexpr int SM_X     = 2048;         // 128 rows x 256 fp16 (kk<128: hi, >=128: lo)
constexpr int SM_W     = SM_X + 128 * 512;       // 67584; 2 layers x 32768 B
constexpr int SM_WSZ   = 32768;
constexpr int SM_TOTAL = SM_W + 2 * SM_WSZ;      // 133120 B
}

// fp16 weights, transposed+swizzled: [W1, W2], each [n][k]
__device__ __align__(16) unsigned char g_Wh[2 * SM_WSZ];

// X tile: row stride 512 B, XOR swizzle on 16B groups within 128B lines
__device__ __forceinline__ uint32_t soff(int r, int kk) {
    return (uint32_t)(r * 512 + (((kk >> 3) ^ (r & 7)) << 4) + (kk & 7) * 2);
}
// W tile: row stride 256 B
__device__ __forceinline__ uint32_t woff(int n, int k) {
    return (uint32_t)(n * 256 + (((k >> 3) ^ (n & 7)) << 4) + (k & 7) * 2);
}

__device__ __forceinline__ uint32_t smem_u32(const void* p) {
    uint32_t a;
    asm("{ .reg .u64 t; cvta.to.shared.u64 t, %1; cvt.u32.u64 %0, t; }"
        : "=r"(a) : "l"(p));
    return a;
}
__device__ __forceinline__ void ldsm_x4(uint32_t* r, uint32_t addr) {
    asm volatile("ldmatrix.sync.aligned.m8n8.x4.shared.b16 {%0,%1,%2,%3}, [%4];"
                 : "=r"(r[0]), "=r"(r[1]), "=r"(r[2]), "=r"(r[3]) : "r"(addr));
}
__device__ __forceinline__ void mma16816(float* d, const uint32_t* a,
                                         const uint32_t* b) {
    asm volatile(
        "mma.sync.aligned.m16n8k16.row.col.f32.f16.f16.f32 "
        "{%0,%1,%2,%3}, {%4,%5,%6,%7}, {%8,%9}, {%0,%1,%2,%3};"
        : "+f"(d[0]), "+f"(d[1]), "+f"(d[2]), "+f"(d[3])
        : "r"(a[0]), "r"(a[1]), "r"(a[2]), "r"(a[3]), "r"(b[0]), "r"(b[1]));
}
__device__ __forceinline__ float elu_f(float x) {
    return x > 0.0f ? x : (__expf(x) - 1.0f);
}
// exact fp16 hi/lo split of a float pair -> two packed half2
__device__ __forceinline__ void split_h2(float a, float b, uint32_t& hi,
                                         uint32_t& lo) {
    const __half ah = __float2half_rn(a);
    const __half bh = __float2half_rn(b);
    __half2 h2 = __halves2half2(ah, bh);
    __half2 l2 = __halves2half2(__float2half_rn(a - __half2float(ah)),
                                __float2half_rn(b - __half2float(bh)));
    hi = *(uint32_t*)&h2;
    lo = *(uint32_t*)&l2;
}

// ---------------- W prep kernel ----------------
__global__ void prep_w_kernel(const float* __restrict__ W1,
                              const float* __restrict__ W2) {
    int idx = blockIdx.x * blockDim.x + threadIdx.x;   // 0 .. 32767
    if (idx >= 2 * 128 * 128) return;
    int l = idx >> 14;
    int e = idx & 16383;
    int n = e >> 7;      // output channel (B row)
    int k = e & 127;     // contraction
    const float* W = l ? W2 : W1;
    float v = W[k * 128 + n];                       // B[n][k] = W[k][n]
    *(__half*)(g_Wh + l * SM_WSZ + woff(n, k)) = __float2half_rn(v);
}

// issue the gather LDGs for one tile into registers
__device__ __forceinline__ void gather_regs(int tile, int tid, bool is64,
                                            const float* __restrict__ f1,
                                            const float* __restrict__ f2,
                                            const void* __restrict__ topk,
                                            float4 pf[8][2]) {
    const int qb = tile * kQPB;
    const int g  = tid & 15;           // 8-float group per row
    #pragma unroll
    for (int it = 0; it < 8; ++it) {
        const int rr = (tid >> 4) + it * 16;       // row 0..127
        const int q  = qb + (rr >> 4);
        const float4* p;
        if (g < 8) {
            const int nb = rr & 15;
            const int gi = is64 ? (int)((const long long*)topk)[q * kNN + nb]
                                : ((const int*)topk)[q * kNN + nb];
            p = (const float4*)(f2 + (size_t)gi * 64) + g * 2;
        } else {
            p = (const float4*)(f1 + (size_t)q * 64) + (g - 8) * 2;
        }
        pf[it][0] = p[0];
        pf[it][1] = p[1];
    }
}

// ---------------- main persistent kernel ----------------
__global__ void __launch_bounds__(kThreads, 1)
fused_mma_kernel(const float* __restrict__ f1, const float* __restrict__ f2,
                 const float* __restrict__ x1, const float* __restrict__ x2,
                 const void* __restrict__ topk,
                 const float* __restrict__ b1, const float* __restrict__ b2,
                 const float* __restrict__ radius, float* __restrict__ out)
{
    extern __shared__ char sm[];
    const uint32_t smb = smem_u32(sm);
    const int tid  = threadIdx.x;
    const int wid  = tid >> 5;
    const int lane = tid & 31;
    __shared__ int s_is64;

    // stage fp16 weights into SMEM once
    {
        const float4* src = (const float4*)g_Wh;
        float4* dst = (float4*)(sm + SM_W);
        #pragma unroll
        for (int i = 0; i < 16; i++) dst[tid + i * 256] = src[tid + i * 256];
    }
    if (tid < 128) {
        ((float*)(sm + SM_B1))[tid] = b1[tid];
        ((float*)(sm + SM_B2))[tid] = b2[tid];
    }
    if (tid < 32) {
        const int* t32 = (const int*)topk;
        unsigned m = __ballot_sync(0xFFFFFFFFu, t32[2 * tid + 1] != 0);
        if (tid == 0) s_is64 = (m == 0u) ? 1 : 0;
    }
    __syncthreads();

    const bool  is64 = (s_is64 != 0);
    const float r    = radius[0];
    const float nid  = -1.0f / (2.0f * r * r);

    const int wrow = (wid & 3) * 32;   // warp tile rows [wrow, wrow+32)
    const int wcol = (wid >> 2) * 64;  // warp tile cols [wcol, wcol+64)
    const int mat  = lane >> 3;        // ldmatrix sub-matrix index
    const int mrow = lane & 7;

    const uint32_t xb = smb + SM_X;

    // prologue: gather tile 0 (this CTA's first tile) into registers
    float4 pf[8][2];
    gather_regs(blockIdx.x, tid, is64, f1, f2, topk, pf);

    for (int tile = blockIdx.x; tile < kTiles; tile += gridDim.x) {
        const int qbase = tile * kQPB;

        __syncthreads();   // prev tile's layer-2 MMA done: X safe to overwrite

        // ---- convert prefetched registers -> Xhi/Xlo halves in smem ----
        {
            const int g = tid & 15;
            #pragma unroll
            for (int it = 0; it < 8; ++it) {
                const int rr = (tid >> 4) + it * 16;
                const float v[8] = {pf[it][0].x, pf[it][0].y, pf[it][0].z, pf[it][0].w,
                                    pf[it][1].x, pf[it][1].y, pf[it][1].z, pf[it][1].w};
                uint4 hi4, lo4;
                uint32_t* hp = (uint32_t*)&hi4;
                uint32_t* lp = (uint32_t*)&lo4;
                #pragma unroll
                for (int j = 0; j < 4; j++)
                    split_h2(v[2 * j], v[2 * j + 1], hp[j], lp[j]);
                *(uint4*)(sm + SM_X + soff(rr, g * 8))       = hi4;
                *(uint4*)(sm + SM_X + soff(rr, g * 8 + 128)) = lo4;
            }
        }
        // ---- per-row distance weights ----
        if (tid < 128) {
            const int q  = qbase + (tid >> 4);
            const int kk = tid & 15;
            int gi = is64 ? (int)((const long long*)topk)[q * kNN + kk]
                          : ((const int*)topk)[q * kNN + kk];
            const float dx = x2[gi * 3 + 0] - x1[q * 3 + 0];
            const float dy = x2[gi * 3 + 1] - x1[q * 3 + 1];
            const float dz = x2[gi * 3 + 2] - x1[q * 3 + 2];
            const float w  = __expf(nid * (dx * dx + dy * dy + dz * dz));
            ((float*)(sm + SM_ROWW))[tid] = (gi == 0) ? 0.0f : w;
        }
        __syncthreads();

        // ---- issue next tile's gather LDGs (hidden under MMA below) ----
        const int nxt = tile + gridDim.x;
        if (nxt < kTiles) gather_regs(nxt, tid, is64, f1, f2, topk, pf);

        float acc[2][8][4];
        #pragma unroll
        for (int i = 0; i < 2; i++)
            #pragma unroll
            for (int j = 0; j < 8; j++)
                #pragma unroll
                for (int e = 0; e < 4; e++) acc[i][j][e] = 0.0f;

        #pragma unroll 1
        for (int layer = 0; layer < 2; ++layer) {
            const uint32_t wb = smb + SM_W + layer * SM_WSZ;

            #pragma unroll 1
            for (int ks = 0; ks < 8; ++ks) {
                // B fragments once per ks, reused by both A halves
                uint32_t bfr[4][4];
                #pragma unroll
                for (int pr = 0; pr < 4; pr++) {
                    const int n  = wcol + pr * 16 + (mat >> 1) * 8 + mrow;
                    const int kk = ks * 16 + (mat & 1) * 8;
                    ldsm_x4(bfr[pr], wb + woff(n, kk));
                }
                #pragma unroll
                for (int hv = 0; hv < 2; hv++) {   // 0: Xhi, 1: Xlo
                    uint32_t afr[2][4];
                    #pragma unroll
                    for (int mt = 0; mt < 2; mt++) {
                        const int row = wrow + mt * 16 + (mat & 1) * 8 + mrow;
                        const int kk  = ks * 16 + hv * 128 + (mat >> 1) * 8;
                        ldsm_x4(afr[mt], xb + soff(row, kk));
                    }
                    #pragma unroll
                    for (int pr = 0; pr < 4; pr++) {
                        #pragma unroll
                        for (int mt = 0; mt < 2; mt++) {
                            mma16816(acc[mt][2 * pr],     afr[mt], bfr[pr]);
                            mma16816(acc[mt][2 * pr + 1], afr[mt], bfr[pr] + 2);
                        }
                    }
                }
            }

            if (layer == 0) {
                __syncthreads();   // all warps done reading X
                // bias + ELU -> exact fp16 split back into X as layer-2 A
                const float* b1s = (const float*)(sm + SM_B1);
                #pragma unroll
                for (int mt = 0; mt < 2; mt++) {
                    const int r0 = wrow + mt * 16 + (lane >> 2);
                    #pragma unroll
                    for (int nt = 0; nt < 8; nt++) {
                        const int c  = wcol + nt * 8 + (lane & 3) * 2;
                        const float bb0 = b1s[c], bb1 = b1s[c + 1];
                        float e0 = elu_f(acc[mt][nt][0] + bb0);
                        float e1 = elu_f(acc[mt][nt][1] + bb1);
                        float e2 = elu_f(acc[mt][nt][2] + bb0);
                        float e3 = elu_f(acc[mt][nt][3] + bb1);
                        uint32_t h0, l0, h1, l1;
                        split_h2(e0, e1, h0, l0);
                        split_h2(e2, e3, h1, l1);
                        *(uint32_t*)(sm + SM_X + soff(r0, c))           = h0;
                        *(uint32_t*)(sm + SM_X + soff(r0, c + 128))     = l0;
                        *(uint32_t*)(sm + SM_X + soff(r0 + 8, c))       = h1;
                        *(uint32_t*)(sm + SM_X + soff(r0 + 8, c + 128)) = l1;
                        acc[mt][nt][0] = 0.0f; acc[mt][nt][1] = 0.0f;
                        acc[mt][nt][2] = 0.0f; acc[mt][nt][3] = 0.0f;
                    }
                }
                __syncthreads();
            }
        }

        // ---- epilogue 2: bias + ELU + weighted 16-row reduce via shuffles ----
        {
            const float* b2s  = (const float*)(sm + SM_B2);
            const float* roww = (const float*)(sm + SM_ROWW);
            #pragma unroll
            for (int mt = 0; mt < 2; mt++) {
                const int q  = (wrow >> 4) + mt;          // query in [0,8)
                const int r0 = wrow + mt * 16 + (lane >> 2);
                const float w0 = roww[r0], w1 = roww[r0 + 8];
                #pragma unroll
                for (int nt = 0; nt < 8; nt++) {
                    const int c  = wcol + nt * 8 + (lane & 3) * 2;
                    const float bb0 = b2s[c], bb1 = b2s[c + 1];
                    float s0 = w0 * elu_f(acc[mt][nt][0] + bb0)
                             + w1 * elu_f(acc[mt][nt][2] + bb0);
                    float s1 = w0 * elu_f(acc[mt][nt][1] + bb1)
                             + w1 * elu_f(acc[mt][nt][3] + bb1);
                    s0 += __shfl_xor_sync(0xFFFFFFFFu, s0, 4);
                    s1 += __shfl_xor_sync(0xFFFFFFFFu, s1, 4);
                    s0 += __shfl_xor_sync(0xFFFFFFFFu, s0, 8);
                    s1 += __shfl_xor_sync(0xFFFFFFFFu, s1, 8);
                    s0 += __shfl_xor_sync(0xFFFFFFFFu, s0, 16);
                    s1 += __shfl_xor_sync(0xFFFFFFFFu, s1, 16);
                    if ((lane >> 2) == 0) {
                        float2 o2 = make_float2(s0, s1);
                        *(float2*)&out[(size_t)(qbase + q) * 128 + c] = o2;
                    }
                }
            }
        }
    }
}

extern "C" void kernel_launch(void* const* d_in, const int* in_sizes, int n_in,
                              void* d_out, int out_size) {
    const float* f1     = (const float*)d_in[0];
    const float* f2     = (const float*)d_in[1];
    const float* x1     = (const float*)d_in[2];
    const float* x2     = (const float*)d_in[3];
    const void*  topk   = d_in[6];
    const float* W1     = (const float*)d_in[7];
    const float* b1     = (const float*)d_in[8];
    const float* W2     = (const float*)d_in[9];
    const float* b2     = (const float*)d_in[10];
    const float* radius = (const float*)d_in[11];
    float* out = (float*)d_out;

    prep_w_kernel<<<128, 256>>>(W1, W2);

    cudaFuncSetAttribute(fused_mma_kernel,
                         cudaFuncAttributeMaxDynamicSharedMemorySize, SM_TOTAL);
    fused_mma_kernel<<<kGrid, kThreads, SM_TOTAL>>>(
        f1, f2, x1, x2, topk, b1, b2, radius, out);
}